// round 8
// baseline (speedup 1.0000x reference)
#include <cuda_runtime.h>
#include <cstdint>

#define B_DIM   2048
#define IN_DIM  4096
#define OUT_DIM 4096
#define FAN     64

#define BT        8          // batch rows per block tile
#define ROWSTRIDE 4100       // words; 4100 % 32 == 4 -> bank = idx + 4*b
#define THREADS   1024       // 32 warps
#define OSPLIT    4
#define OCHUNK    (OUT_DIM / OSPLIT)   // 1024 outputs per block
#define OPP       128                  // 32 warps * 4 outputs per pass
#define NPASS     (OCHUNK / OPP)       // 8
#define NQUAD     (OUT_DIM / 4)        // 1024

// Pack layout (u64 units), per quad of outputs {4q..4q+3}:
//   g_pack[q*256 + f2*8 + g*2 + {0,1}]  = (weight<<32 | idx) for steps 2*f2, 2*f2+1
// -> one warp f2-step reads 64 contiguous bytes (1 L1 line per 2 steps).
__device__ unsigned long long g_pack[OUT_DIM * FAN];

// ---------------------------------------------------------------------------
// Prep: one thread per QUAD of outputs (the 4 outputs sharing a warp group).
// 1) counting-sort each output's 64 (idx,w) pairs by idx&3 (= smem bank class
//    under ROWSTRIDE=4100).
// 2) greedy per-step class matching across the 4 groups: at each of the 64
//    steps, assign each group a class, preferring classes unused this step
//    (most-skewed group picks first). Distinct classes -> conflict-free LDS.
// Pure permutation of each output's summation order -> numerically exact.
//
// Mask dtype is detected on device (JAX may ship int32 despite int64 in the
// reference): for int64 values < 4096 every odd 32-bit word is zero.
// ---------------------------------------------------------------------------
__global__ void prep_kernel(const float* __restrict__ w,
                            const unsigned* __restrict__ m32) {
    int q = blockIdx.x * blockDim.x + threadIdx.x;
    if (q >= NQUAD) return;

    unsigned odd_or = 0;
    #pragma unroll
    for (int i = 1; i < 16; i += 2) odd_or |= m32[i];
    const unsigned sh = (odd_or == 0u) ? 1u : 0u;   // 1 -> int64, 0 -> int32

    unsigned long long sorted[4][FAN];
    int rem[4][4], pos[4][4];

    for (int g = 0; g < 4; g++) {
        const size_t base = (size_t)(q * 4 + g) * FAN;
        int cnt[4] = {0, 0, 0, 0};
        for (int f = 0; f < FAN; f++)
            cnt[m32[(base + f) << sh] & 3u]++;
        int st[4];
        st[0] = 0; st[1] = cnt[0]; st[2] = cnt[0] + cnt[1]; st[3] = cnt[0] + cnt[1] + cnt[2];
        int cur[4] = {st[0], st[1], st[2], st[3]};
        for (int f = 0; f < FAN; f++) {
            unsigned idx = m32[(base + f) << sh];
            unsigned wb  = __float_as_uint(w[base + f]);
            sorted[g][cur[idx & 3]++] = ((unsigned long long)wb << 32) | idx;
        }
        for (int c = 0; c < 4; c++) { rem[g][c] = cnt[c]; pos[g][c] = st[c]; }
    }

    const size_t qbase = (size_t)q * 256;
    for (int t = 0; t < FAN; t++) {
        // order groups by max remaining class count, descending (most skewed first)
        int key[4], order[4];
        for (int g = 0; g < 4; g++) {
            int m = rem[g][0];
            for (int c = 1; c < 4; c++) if (rem[g][c] > m) m = rem[g][c];
            key[g] = m; order[g] = g;
        }
        for (int i = 1; i < 4; i++) {
            int kg = key[i], og = order[i], j = i;
            while (j > 0 && key[j-1] < kg) { key[j] = key[j-1]; order[j] = order[j-1]; j--; }
            key[j] = kg; order[j] = og;
        }
        int used = 0;
        for (int s = 0; s < 4; s++) {
            int g = order[s];
            int best = -1;
            for (int c = 0; c < 4; c++)                 // prefer unused classes
                if (rem[g][c] > 0 && !((used >> c) & 1) &&
                    (best < 0 || rem[g][c] > rem[g][best])) best = c;
            if (best < 0)                               // forced collision
                for (int c = 0; c < 4; c++)
                    if (rem[g][c] > 0 && (best < 0 || rem[g][c] > rem[g][best])) best = c;
            g_pack[qbase + (size_t)((t >> 1) * 8 + g * 2 + (t & 1))] =
                sorted[g][pos[g][best]++];
            rem[g][best]--;
            used |= 1 << best;
        }
    }
}

// ---------------------------------------------------------------------------
// Main gather kernel.
//   smem tile: 8 batch rows, row stride 4100 words  (bank = idx + 4*b)
//   warp = 4 output-groups (lane>>3) x 8 batch lanes (lane&7)
//   per f2-step: one LDG.128 spanning a single 128B line (interleaved pack),
//   two class-scheduled conflict-minimized LDS gathers, two fp32 FMAs.
//   One barrier per block, none in the pass loop.
// ---------------------------------------------------------------------------
__global__ __launch_bounds__(THREADS, 1)
void gather_kernel(const float* __restrict__ input,
                   const float* __restrict__ bias,
                   float* __restrict__ out) {
    extern __shared__ float tile[];    // BT * ROWSTRIDE floats = 131200 B

    const int tid   = threadIdx.x;
    const int wid   = tid >> 5;
    const int lane  = tid & 31;
    const int brow0 = blockIdx.x * BT;
    const int obase = blockIdx.y * OCHUNK;

    // ---- load 8 input rows into smem (4 warps per row, float4, conflict-free)
    {
        int r = wid >> 2;
        const float4* src = (const float4*)(input + (size_t)(brow0 + r) * IN_DIM);
        float* dst = tile + r * ROWSTRIDE;
        #pragma unroll
        for (int j = (wid & 3) * 32 + lane; j < IN_DIM / 4; j += 128) {
            float4 v = src[j];
            *(float4*)(dst + 4 * j) = v;
        }
    }
    __syncthreads();

    const int g  = lane >> 3;          // output group within warp (== o & 3)
    const int bb = lane & 7;           // batch lane
    const float* srow = tile + bb * ROWSTRIDE;

    for (int pass = 0; pass < NPASS; pass++) {
        const int q = (obase >> 2) + pass * (OPP / 4) + wid;   // quad id
        const int o = q * 4 + g;
        const ulonglong2* pk = (const ulonglong2*)(g_pack + (size_t)q * 256);

        float acc0 = 0.f, acc1 = 0.f;
        #pragma unroll 8
        for (int f2 = 0; f2 < FAN / 2; f2++) {
            ulonglong2 v = pk[f2 * 4 + g];         // 64B/warp, one 128B line / 2 steps
            unsigned ia = (unsigned)v.x;
            float    wa = __uint_as_float((unsigned)(v.x >> 32));
            unsigned ib = (unsigned)v.y;
            float    wb = __uint_as_float((unsigned)(v.y >> 32));
            acc0 = fmaf(srow[ia], wa, acc0);
            acc1 = fmaf(srow[ib], wb, acc1);
        }
        out[(size_t)(brow0 + bb) * OUT_DIM + o] = acc0 + acc1 + bias[o];
    }
}

// ---------------------------------------------------------------------------
// Harness entry. Inputs (metadata order):
//   0: input            float32 [2048, 4096]
//   1: condensed_weight float32 [4096, 64]
//   2: bias             float32 [4096]
//   3: input_mask       int64-or-int32 [4096, 64]  (detected on device)
// Output: float32 [2048, 4096]
// ---------------------------------------------------------------------------
extern "C" void kernel_launch(void* const* d_in, const int* in_sizes, int n_in,
                              void* d_out, int out_size) {
    const float*    input  = (const float*)d_in[0];
    const float*    weight = (const float*)d_in[1];
    const float*    bias   = (const float*)d_in[2];
    const unsigned* mask32 = (const unsigned*)d_in[3];
    float*          out    = (float*)d_out;
    (void)in_sizes; (void)n_in; (void)out_size;

    prep_kernel<<<NQUAD / 256, 256>>>(weight, mask32);

    const int smem_bytes = BT * ROWSTRIDE * (int)sizeof(float);   // 131200
    cudaFuncSetAttribute(gather_kernel,
                         cudaFuncAttributeMaxDynamicSharedMemorySize, smem_bytes);

    dim3 grid(B_DIM / BT, OSPLIT);
    gather_kernel<<<grid, THREADS, smem_bytes>>>(input, bias, out);
}

// round 9
// speedup vs baseline: 1.7095x; 1.7095x over previous
#include <cuda_runtime.h>
#include <cstdint>

#define B_DIM   2048
#define IN_DIM  4096
#define OUT_DIM 4096
#define FAN     64

#define BT        8          // batch rows per block tile
#define ROWSTRIDE 4100       // words; 4100 % 32 == 4 -> bank = idx + 4*b
#define THREADS   1024       // 32 warps
#define OSPLIT    4
#define OCHUNK    (OUT_DIM / OSPLIT)   // 1024 outputs per block
#define OPP       128                  // 32 warps * 4 outputs per pass
#define NPASS     (OCHUNK / OPP)       // 8
#define NQUAD     (OUT_DIM / 4)        // 1024

// Final pack layout (u64 units), per quad of outputs {4q..4q+3}:
//   g_pack[q*256 + f2*8 + g*2 + {0,1}] = (weight<<32 | idx) for steps 2f2, 2f2+1
// -> one warp f2-step reads 64 contiguous bytes (1 L1 line per 2 steps).
__device__ unsigned long long g_pack[OUT_DIM * FAN];

// Scratch between prep phases: class-sorted pairs + per-output class counts.
__device__ unsigned long long g_sorted[OUT_DIM * FAN];
__device__ int                g_cnt[OUT_DIM * 4];

// ---------------------------------------------------------------------------
// Prep phase A: one thread per OUTPUT (4096 threads).
// Counting-sort the 64 (idx,w) pairs by idx&3 (= smem bank class under
// ROWSTRIDE=4100) into g_sorted; publish class counts. Registers only.
//
// Mask dtype detected on device (JAX may ship int32 despite int64 in the
// reference): for int64 values < 4096 every odd 32-bit word is zero.
// ---------------------------------------------------------------------------
__global__ void prepA_kernel(const float* __restrict__ w,
                             const unsigned* __restrict__ m32) {
    int o = blockIdx.x * blockDim.x + threadIdx.x;
    if (o >= OUT_DIM) return;

    unsigned odd_or = 0;
    #pragma unroll
    for (int i = 1; i < 16; i += 2) odd_or |= m32[i];
    const unsigned sh = (odd_or == 0u) ? 1u : 0u;   // 1 -> int64, 0 -> int32

    const size_t base = (size_t)o * FAN;

    int c0 = 0, c1 = 0, c2 = 0, c3 = 0;
    #pragma unroll 4
    for (int f = 0; f < FAN; f++) {
        unsigned c = m32[(base + f) << sh] & 3u;
        c0 += (c == 0); c1 += (c == 1); c2 += (c == 2); c3 += (c == 3);
    }
    int cur[4];
    cur[0] = 0; cur[1] = c0; cur[2] = c0 + c1; cur[3] = c0 + c1 + c2;

    #pragma unroll 4
    for (int f = 0; f < FAN; f++) {
        unsigned idx = m32[(base + f) << sh];
        unsigned wb  = __float_as_uint(w[base + f]);
        g_sorted[base + cur[idx & 3]++] = ((unsigned long long)wb << 32) | idx;
    }
    g_cnt[o * 4 + 0] = c0;
    g_cnt[o * 4 + 1] = c1;
    g_cnt[o * 4 + 2] = c2;
    g_cnt[o * 4 + 3] = c3;
}

// ---------------------------------------------------------------------------
// Prep phase B: one thread per QUAD (1024 threads, 16 blocks).
// Greedy per-step class matching across the quad's 4 groups (identical
// schedule to the validated R8 version: most-skewed group picks first,
// prefer classes unused this step). The schedule depends only on the class
// COUNTS, so per-thread state is 32 ints; the 2KB value arrays stay in L2.
// Pure permutation of each output's summation order -> numerically exact.
// ---------------------------------------------------------------------------
__global__ void prepB_kernel() {
    int q = blockIdx.x * blockDim.x + threadIdx.x;
    if (q >= NQUAD) return;

    int rem[4][4];
    int pos[4][4];   // absolute u64 index into g_sorted
    for (int g = 0; g < 4; g++) {
        const int o = q * 4 + g;
        int cc0 = g_cnt[o * 4 + 0];
        int cc1 = g_cnt[o * 4 + 1];
        int cc2 = g_cnt[o * 4 + 2];
        int cc3 = g_cnt[o * 4 + 3];
        rem[g][0] = cc0; rem[g][1] = cc1; rem[g][2] = cc2; rem[g][3] = cc3;
        int b = o * FAN;
        pos[g][0] = b;
        pos[g][1] = b + cc0;
        pos[g][2] = b + cc0 + cc1;
        pos[g][3] = b + cc0 + cc1 + cc2;
    }

    const size_t qbase = (size_t)q * 256;
    for (int t = 0; t < FAN; t++) {
        // order groups by max remaining class count, descending
        int key[4], order[4];
        for (int g = 0; g < 4; g++) {
            int m = rem[g][0];
            for (int c = 1; c < 4; c++) if (rem[g][c] > m) m = rem[g][c];
            key[g] = m; order[g] = g;
        }
        for (int i = 1; i < 4; i++) {
            int kg = key[i], og = order[i], j = i;
            while (j > 0 && key[j-1] < kg) { key[j] = key[j-1]; order[j] = order[j-1]; j--; }
            key[j] = kg; order[j] = og;
        }
        int used = 0;
        for (int s = 0; s < 4; s++) {
            int g = order[s];
            int best = -1;
            for (int c = 0; c < 4; c++)                 // prefer unused classes
                if (rem[g][c] > 0 && !((used >> c) & 1) &&
                    (best < 0 || rem[g][c] > rem[g][best])) best = c;
            if (best < 0)                               // forced collision
                for (int c = 0; c < 4; c++)
                    if (rem[g][c] > 0 && (best < 0 || rem[g][c] > rem[g][best])) best = c;
            g_pack[qbase + (size_t)((t >> 1) * 8 + g * 2 + (t & 1))] =
                g_sorted[pos[g][best]++];
            rem[g][best]--;
            used |= 1 << best;
        }
    }
}

// ---------------------------------------------------------------------------
// Main gather kernel (identical to the validated 211us R8 version).
//   smem tile: 8 batch rows, row stride 4100 words  (bank = idx + 4*b)
//   warp = 4 output-groups (lane>>3) x 8 batch lanes (lane&7)
//   per f2-step: one LDG.128 from a single 128B line (interleaved pack),
//   two class-scheduled conflict-minimized LDS gathers, two fp32 FMAs.
//   One barrier per block, none in the pass loop.
// ---------------------------------------------------------------------------
__global__ __launch_bounds__(THREADS, 1)
void gather_kernel(const float* __restrict__ input,
                   const float* __restrict__ bias,
                   float* __restrict__ out) {
    extern __shared__ float tile[];    // BT * ROWSTRIDE floats = 131200 B

    const int tid   = threadIdx.x;
    const int wid   = tid >> 5;
    const int lane  = tid & 31;
    const int brow0 = blockIdx.x * BT;
    const int obase = blockIdx.y * OCHUNK;

    // ---- load 8 input rows into smem (4 warps per row, float4, conflict-free)
    {
        int r = wid >> 2;
        const float4* src = (const float4*)(input + (size_t)(brow0 + r) * IN_DIM);
        float* dst = tile + r * ROWSTRIDE;
        #pragma unroll
        for (int j = (wid & 3) * 32 + lane; j < IN_DIM / 4; j += 128) {
            float4 v = src[j];
            *(float4*)(dst + 4 * j) = v;
        }
    }
    __syncthreads();

    const int g  = lane >> 3;          // output group within warp (== o & 3)
    const int bb = lane & 7;           // batch lane
    const float* srow = tile + bb * ROWSTRIDE;

    for (int pass = 0; pass < NPASS; pass++) {
        const int q = (obase >> 2) + pass * (OPP / 4) + wid;   // quad id
        const int o = q * 4 + g;
        const ulonglong2* pk = (const ulonglong2*)(g_pack + (size_t)q * 256);

        float acc0 = 0.f, acc1 = 0.f;
        #pragma unroll 8
        for (int f2 = 0; f2 < FAN / 2; f2++) {
            ulonglong2 v = pk[f2 * 4 + g];         // 64B/warp, one 128B line / 2 steps
            unsigned ia = (unsigned)v.x;
            float    wa = __uint_as_float((unsigned)(v.x >> 32));
            unsigned ib = (unsigned)v.y;
            float    wb = __uint_as_float((unsigned)(v.y >> 32));
            acc0 = fmaf(srow[ia], wa, acc0);
            acc1 = fmaf(srow[ib], wb, acc1);
        }
        out[(size_t)(brow0 + bb) * OUT_DIM + o] = acc0 + acc1 + bias[o];
    }
}

// ---------------------------------------------------------------------------
// Harness entry. Inputs (metadata order):
//   0: input            float32 [2048, 4096]
//   1: condensed_weight float32 [4096, 64]
//   2: bias             float32 [4096]
//   3: input_mask       int64-or-int32 [4096, 64]  (detected on device)
// Output: float32 [2048, 4096]
// ---------------------------------------------------------------------------
extern "C" void kernel_launch(void* const* d_in, const int* in_sizes, int n_in,
                              void* d_out, int out_size) {
    const float*    input  = (const float*)d_in[0];
    const float*    weight = (const float*)d_in[1];
    const float*    bias   = (const float*)d_in[2];
    const unsigned* mask32 = (const unsigned*)d_in[3];
    float*          out    = (float*)d_out;
    (void)in_sizes; (void)n_in; (void)out_size;

    prepA_kernel<<<OUT_DIM / 256, 256>>>(weight, mask32);
    prepB_kernel<<<16, NQUAD / 16>>>();

    const int smem_bytes = BT * ROWSTRIDE * (int)sizeof(float);   // 131200
    cudaFuncSetAttribute(gather_kernel,
                         cudaFuncAttributeMaxDynamicSharedMemorySize, smem_bytes);

    dim3 grid(B_DIM / BT, OSPLIT);
    gather_kernel<<<grid, THREADS, smem_bytes>>>(input, bias, out);
}

// round 10
// speedup vs baseline: 2.2264x; 1.3024x over previous
#include <cuda_runtime.h>
#include <cstdint>

#define B_DIM   2048
#define IN_DIM  4096
#define OUT_DIM 4096
#define FAN     64

#define BT        8          // batch rows per block tile
#define ROWSTRIDE 4100       // words; 4100 % 32 == 4 -> bank = idx + 4*b
#define THREADS   1024       // 32 warps
#define OSPLIT    4
#define OCHUNK    (OUT_DIM / OSPLIT)   // 1024 outputs per block
#define OPP       128                  // 32 warps * 4 outputs per pass
#define NPASS     (OCHUNK / OPP)       // 8
#define NQUAD     (OUT_DIM / 4)        // 1024

// Final pack layout (u64 units), per quad of outputs {4q..4q+3}:
//   g_pack[q*256 + f2*8 + g*2 + {0,1}] = (weight<<32 | idx) for steps 2f2, 2f2+1
// -> one warp f2-step reads 64 contiguous bytes (1 L1 line per 2 steps).
__device__ unsigned long long g_pack[OUT_DIM * FAN];

// Scratch between prep phases: class-sorted pairs + per-output class counts.
__device__ unsigned long long g_sorted[OUT_DIM * FAN];
__device__ int                g_cnt[OUT_DIM * 4];

// ---------------------------------------------------------------------------
// Prep phase A: one thread per OUTPUT. Counting-sort the 64 (idx,w) pairs by
// idx&3 (= smem bank class under ROWSTRIDE=4100) into g_sorted; publish class
// counts. Register-only: class cursors kept in 4 scalars via select chains
// (no runtime-indexed arrays -> no local-memory traffic).
//
// Mask dtype detected on device (JAX may ship int32 despite int64 in the
// reference): for int64 values < 4096 every odd 32-bit word is zero.
// ---------------------------------------------------------------------------
__global__ void prepA_kernel(const float* __restrict__ w,
                             const unsigned* __restrict__ m32) {
    int o = blockIdx.x * blockDim.x + threadIdx.x;
    if (o >= OUT_DIM) return;

    unsigned odd_or = 0;
    #pragma unroll
    for (int i = 1; i < 16; i += 2) odd_or |= m32[i];
    const unsigned sh = (odd_or == 0u) ? 1u : 0u;   // 1 -> int64, 0 -> int32

    const size_t base = (size_t)o * FAN;

    int c0 = 0, c1 = 0, c2 = 0, c3 = 0;
    #pragma unroll 8
    for (int f = 0; f < FAN; f++) {
        unsigned c = m32[(base + f) << sh] & 3u;
        c0 += (c == 0); c1 += (c == 1); c2 += (c == 2); c3 += (c == 3);
    }
    int cur0 = 0, cur1 = c0, cur2 = c0 + c1, cur3 = c0 + c1 + c2;

    #pragma unroll 8
    for (int f = 0; f < FAN; f++) {
        unsigned idx = m32[(base + f) << sh];
        unsigned wb  = __float_as_uint(w[base + f]);
        unsigned c   = idx & 3u;
        int p = (c == 0) ? cur0 : (c == 1) ? cur1 : (c == 2) ? cur2 : cur3;
        g_sorted[base + p] = ((unsigned long long)wb << 32) | idx;
        cur0 += (c == 0); cur1 += (c == 1); cur2 += (c == 2); cur3 += (c == 3);
    }
    g_cnt[o * 4 + 0] = c0;
    g_cnt[o * 4 + 1] = c1;
    g_cnt[o * 4 + 2] = c2;
    g_cnt[o * 4 + 3] = c3;
}

// ---------------------------------------------------------------------------
// Prep phase B: one thread per QUAD. Greedy per-step class matching across
// the quad's 4 groups: fixed group order; each group takes its max-remaining
// class among classes not yet used this step (fallback: overall max). Fully
// unrolled g/c loops + predicated "best" application keep rem[][]/pos[][] in
// registers (no local memory). Pure permutation of each output's summation
// order -> numerically exact; distinct classes -> conflict-free LDS.
// ---------------------------------------------------------------------------
__global__ void prepB_kernel() {
    int q = blockIdx.x * blockDim.x + threadIdx.x;
    if (q >= NQUAD) return;

    int rem[4][4];
    int pos[4][4];   // absolute u64 index into g_sorted
    #pragma unroll
    for (int g = 0; g < 4; g++) {
        const int o = q * 4 + g;
        int cc0 = g_cnt[o * 4 + 0];
        int cc1 = g_cnt[o * 4 + 1];
        int cc2 = g_cnt[o * 4 + 2];
        int cc3 = g_cnt[o * 4 + 3];
        rem[g][0] = cc0; rem[g][1] = cc1; rem[g][2] = cc2; rem[g][3] = cc3;
        int b = o * FAN;
        pos[g][0] = b;
        pos[g][1] = b + cc0;
        pos[g][2] = b + cc0 + cc1;
        pos[g][3] = b + cc0 + cc1 + cc2;
    }

    const size_t qbase = (size_t)q * 256;
    for (int t = 0; t < FAN; t++) {
        int used = 0;
        #pragma unroll
        for (int g = 0; g < 4; g++) {
            // pick max-remaining class among unused-this-step classes
            int best = -1, bc = 0;
            #pragma unroll
            for (int c = 0; c < 4; c++) {
                bool av = (rem[g][c] > 0) && !((used >> c) & 1);
                if (av && rem[g][c] > bc) { best = c; bc = rem[g][c]; }
            }
            if (best < 0) {               // forced collision: overall max
                #pragma unroll
                for (int c = 0; c < 4; c++)
                    if (rem[g][c] > bc) { best = c; bc = rem[g][c]; }
            }
            int p = 0;
            #pragma unroll
            for (int c = 0; c < 4; c++)
                if (c == best) { p = pos[g][c]; pos[g][c] = p + 1; rem[g][c]--; }
            g_pack[qbase + (size_t)((t >> 1) * 8 + g * 2 + (t & 1))] = g_sorted[p];
            used |= 1 << best;
        }
    }
}

// ---------------------------------------------------------------------------
// Main gather kernel.
//   smem tile: 8 batch rows, row stride 4100 words  (bank = idx + 4*b)
//   warp = 4 output-groups (lane&3) x 8 batch lanes (lane>>2)
//     -> stores: 4 consecutive outputs x 8 rows = 8 lines/STG (was 32)
//     -> LDS banks: idx_g + 4*bb, distinct classes across g => conflict-free
//   per f2-step: one LDG.128 from a single 128B line (interleaved pack),
//   two class-scheduled LDS gathers, two fp32 FMAs.
//   One barrier per block, none in the pass loop.
// ---------------------------------------------------------------------------
__global__ __launch_bounds__(THREADS, 1)
void gather_kernel(const float* __restrict__ input,
                   const float* __restrict__ bias,
                   float* __restrict__ out) {
    extern __shared__ float tile[];    // BT * ROWSTRIDE floats = 131200 B

    const int tid   = threadIdx.x;
    const int wid   = tid >> 5;
    const int lane  = tid & 31;
    const int brow0 = blockIdx.x * BT;
    const int obase = blockIdx.y * OCHUNK;

    // ---- load 8 input rows into smem (4 warps per row, float4, conflict-free)
    {
        int r = wid >> 2;
        const float4* src = (const float4*)(input + (size_t)(brow0 + r) * IN_DIM);
        float* dst = tile + r * ROWSTRIDE;
        #pragma unroll
        for (int j = (wid & 3) * 32 + lane; j < IN_DIM / 4; j += 128) {
            float4 v = src[j];
            *(float4*)(dst + 4 * j) = v;
        }
    }
    __syncthreads();

    const int g  = lane & 3;           // output group within warp (== o & 3)
    const int bb = lane >> 2;          // batch lane
    const float* srow = tile + bb * ROWSTRIDE;

    for (int pass = 0; pass < NPASS; pass++) {
        const int q = (obase >> 2) + pass * (OPP / 4) + wid;   // quad id
        const int o = q * 4 + g;
        const ulonglong2* pk = (const ulonglong2*)(g_pack + (size_t)q * 256);

        float acc0 = 0.f, acc1 = 0.f;
        #pragma unroll 8
        for (int f2 = 0; f2 < FAN / 2; f2++) {
            ulonglong2 v = pk[f2 * 4 + g];         // 64B/warp, one 128B line / 2 steps
            unsigned ia = (unsigned)v.x;
            float    wa = __uint_as_float((unsigned)(v.x >> 32));
            unsigned ib = (unsigned)v.y;
            float    wb = __uint_as_float((unsigned)(v.y >> 32));
            acc0 = fmaf(srow[ia], wa, acc0);
            acc1 = fmaf(srow[ib], wb, acc1);
        }
        out[(size_t)(brow0 + bb) * OUT_DIM + o] = acc0 + acc1 + bias[o];
    }
}

// ---------------------------------------------------------------------------
// Harness entry. Inputs (metadata order):
//   0: input            float32 [2048, 4096]
//   1: condensed_weight float32 [4096, 64]
//   2: bias             float32 [4096]
//   3: input_mask       int64-or-int32 [4096, 64]  (detected on device)
// Output: float32 [2048, 4096]
// ---------------------------------------------------------------------------
extern "C" void kernel_launch(void* const* d_in, const int* in_sizes, int n_in,
                              void* d_out, int out_size) {
    const float*    input  = (const float*)d_in[0];
    const float*    weight = (const float*)d_in[1];
    const float*    bias   = (const float*)d_in[2];
    const unsigned* mask32 = (const unsigned*)d_in[3];
    float*          out    = (float*)d_out;
    (void)in_sizes; (void)n_in; (void)out_size;

    prepA_kernel<<<128, 32>>>(weight, mask32);   // 4096 threads, 128 blocks
    prepB_kernel<<<32, 32>>>();                  // 1024 threads, 32 blocks

    const int smem_bytes = BT * ROWSTRIDE * (int)sizeof(float);   // 131200
    cudaFuncSetAttribute(gather_kernel,
                         cudaFuncAttributeMaxDynamicSharedMemorySize, smem_bytes);

    dim3 grid(B_DIM / BT, OSPLIT);
    gather_kernel<<<grid, THREADS, smem_bytes>>>(input, bias, out);
}